// round 15
// baseline (speedup 1.0000x reference)
#include <cuda_runtime.h>

#define TT 300

// ---------------- static scratch (no allocations allowed) ----------------
__device__ float g_a [78643200];   // conv outputs (max: layer1, 16*16*32*32*300)
__device__ float g_sA[78643200];   // ping buffer
__device__ float g_sB[19660800];   // pong buffer
__device__ float g_u [48000];      // dense pre-psp output (combined)
__device__ float g_up[192000];     // dense split-K partials (4 x 48000)

// ---------------- double-float constant splits (compile-time folded) ------
constexpr double DDd   = 0.9048374180359595;     // exp(-0.1)
constexpr double D2d   = 0.8187307530779818;     // exp(-0.2)
constexpr double TD2d  = 1.6374615061559637;     // 2*exp(-0.2)
constexpr double CC1d  = 0.2718281828459045;     // e/10
constexpr double CC1Dd = CC1d * DDd;             // (e/10)*exp(-0.1)
constexpr double CC2d  = 1.2340980408667956e-3;  // 10*exp(-9)
constexpr double CC3d  = 1.2340980408667956e-5;  // 0.1*exp(-9)
constexpr float DD_H   = (float)DDd;
constexpr float DD_L   = (float)(DDd   - (double)DD_H);
constexpr float D2_H   = (float)D2d;
constexpr float D2_L   = (float)(D2d   - (double)D2_H);
constexpr float TD2_H  = (float)TD2d;
constexpr float TD2_L  = (float)(TD2d  - (double)TD2_H);
constexpr float CC1_H  = (float)CC1d;
constexpr float CC1_L  = (float)(CC1d  - (double)CC1_H);
constexpr float CC1D_H = (float)CC1Dd;
constexpr float CC1D_L = (float)(CC1Dd - (double)CC1D_H);
constexpr float CC2_H  = (float)CC2d;
constexpr float CC2_L  = (float)(CC2d  - (double)CC2_H);
constexpr float CC3_H  = (float)CC3d;

// ---------------- double-float (two-float) primitives ---------------------
struct df { float h, l; };

__device__ __forceinline__ df df_add(df a, df b) {
    float s  = a.h + b.h;
    float bb = s - a.h;
    float e  = (a.h - (s - bb)) + (b.h - bb);
    e += a.l + b.l;
    float h = s + e;
    float l = e - (h - s);
    return {h, l};
}
__device__ __forceinline__ df df_addf(df a, float b) {
    float s  = a.h + b;
    float bb = s - a.h;
    float e  = (a.h - (s - bb)) + (b - bb);
    e += a.l;
    float h = s + e;
    float l = e - (h - s);
    return {h, l};
}
__device__ __forceinline__ df df_mulc(df a, float ch, float cl) {
    float p = a.h * ch;
    float e = fmaf(a.h, ch, -p);
    e = fmaf(a.h, cl, e);
    e = fmaf(a.l, ch, e);
    float h = p + e;
    float l = e - (h - p);
    return {h, l};
}

// =====================================================================
// Spatial conv: t-COARSENED x2 (float2 I/O; weight-LDS amortized over 2
// timesteps — the R13 perf win) + NL=2 LANE-SPLIT accumulators with exact
// Neumaier combine (the R12 numerics: per-lane chains of <=CI/2*KH*KW terms,
// BIT-IDENTICAL per output to the R12 build that scored rel_err = 0.0).
// R13 proved single 144/288-term chains flip the knife-edge neuron
// (signature rel_err 1.718147e-2) — lane split is load-bearing.
// threads = 160 (2 t each); z = b + 16*co_group.
// =====================================================================
template<int CI,int NL,int CO_T,int CO_FULL,int KH,int KW,int HIN,int WIN,int HOUT,int WOUT,int PAD>
__global__ void __launch_bounds__(160, 3)
conv_kernel(const float* __restrict__ in, const float* __restrict__ w,
            float* __restrict__ out)
{
    __shared__ __align__(16) float sw[CI*KH*KW*CO_T];
    const int tid = threadIdx.x;
    const int ow = blockIdx.x, oh = blockIdx.y;
    const int b = blockIdx.z & 15;
    const int co_base = (blockIdx.z >> 4) * CO_T;

    for (int i = tid; i < CI*KH*KW*CO_T; i += 160) {
        int k = i / CO_T, co = i % CO_T;
        sw[i] = w[(co_base + co)*(CI*KH*KW) + k];
    }
    __syncthreads();

    const int t = tid * 2;
    if (t >= TT) return;

    float acc0[NL][CO_T], acc1[NL][CO_T];
#pragma unroll
    for (int l = 0; l < NL; l++)
#pragma unroll
        for (int c = 0; c < CO_T; c++) { acc0[l][c] = 0.f; acc1[l][c] = 0.f; }

    for (int g = 0; g < CI/NL; g++) {
#pragma unroll
        for (int l = 0; l < NL; l++) {
            const int ci = g*NL + l;
            // ---- batched float2 load phase for this (g,l) ----
            float2 xv[KH*KW];
#pragma unroll
            for (int kh = 0; kh < KH; kh++) {
                const int ih = oh + kh - PAD;
#pragma unroll
                for (int kw = 0; kw < KW; kw++) {
                    const int iw = ow + kw - PAD;
                    const bool valid = ((unsigned)ih < (unsigned)HIN) && ((unsigned)iw < (unsigned)WIN);
                    float2 v = {0.f, 0.f};
                    if (valid)
                        v = *reinterpret_cast<const float2*>(
                                in + ((((b*CI + ci)*HIN + ih)*WIN) + iw)*TT + t);
                    xv[kh*KW + kw] = v;
                }
            }
            // ---- FMA burst: each weight LDS feeds 2 timesteps ----
#pragma unroll
            for (int k = 0; k < KH*KW; k++) {
                const float x0 = xv[k].x, x1 = xv[k].y;
                const float4* wv = reinterpret_cast<const float4*>(&sw[(ci*KH*KW + k)*CO_T]);
#pragma unroll
                for (int c4 = 0; c4 < CO_T/4; c4++) {
                    float4 wq = wv[c4];
                    acc0[l][c4*4+0] = fmaf(wq.x, x0, acc0[l][c4*4+0]);
                    acc1[l][c4*4+0] = fmaf(wq.x, x1, acc1[l][c4*4+0]);
                    acc0[l][c4*4+1] = fmaf(wq.y, x0, acc0[l][c4*4+1]);
                    acc1[l][c4*4+1] = fmaf(wq.y, x1, acc1[l][c4*4+1]);
                    acc0[l][c4*4+2] = fmaf(wq.z, x0, acc0[l][c4*4+2]);
                    acc1[l][c4*4+2] = fmaf(wq.z, x1, acc1[l][c4*4+2]);
                    acc0[l][c4*4+3] = fmaf(wq.w, x0, acc0[l][c4*4+3]);
                    acc1[l][c4*4+3] = fmaf(wq.w, x1, acc1[l][c4*4+3]);
                }
            }
        }
    }

    // exact Neumaier combine across lanes (once per output) — as in R12
#pragma unroll
    for (int c = 0; c < CO_T; c++) {
        float s0  = acc0[0][c], cmp0 = 0.f;
        float s1  = acc1[0][c], cmp1 = 0.f;
#pragma unroll
        for (int l = 1; l < NL; l++) {
            {
                float bv = acc0[l][c];
                float tv = s0 + bv;
                float bb = tv - s0;
                cmp0 += (s0 - (tv - bb)) + (bv - bb);
                s0 = tv;
            }
            {
                float bv = acc1[l][c];
                float tv = s1 + bv;
                float bb = tv - s1;
                cmp1 += (s1 - (tv - bb)) + (bv - bb);
                s1 = tv;
            }
        }
        float* q = out + ((((b*CO_FULL) + (co_base + c))*HOUT + oh)*WOUT + ow)*TT + t;
        *reinterpret_cast<float2*>(q) = make_float2(s0 + cmp0, s1 + cmp1);
    }
}

// =====================================================================
// PSP (2-step-blocked double-float IIR + fp32 delayed-tail IIR) fused with
// the bit-exact refractory scan, and (POOLW>0) the SLAYER 2x2 sum-pool
// (11 * sum of 4 binary spikes — exact in fp32, any order).
// POOLW = spatial row width (32 or 16); POOLW=0 -> plain spike output.
// 128 neurons/block; 32-t tiles; float4 staged I/O; next-tile prefetch.
// =====================================================================
template<int POOLW>
__global__ void __launch_bounds__(128)
psp_spike_kernel(const float* __restrict__ a, float* __restrict__ s, int N)
{
    __shared__ __align__(16) float sx[128][36];   // current tile (spikes in-place)
    __shared__ __align__(16) float sd[128][36];   // 100-delayed tile
    const int tid = threadIdx.x;
    const int n0 = blockIdx.x * 128;
    const int n  = n0 + tid;

    df Z = {0.f, 0.f}, P = {0.f, 0.f};
    float Z2t = 0.f, P2t = 0.f;
    float r   = 0.f;

    float4 curv[8], delv[8];

    // ---- prefetch tile 0 ----
#pragma unroll
    for (int q = 0; q < 8; q++) {
        const int flat = q*128 + tid;
        const int row = flat >> 3, c4 = flat & 7;
        const int nn = n0 + row;
        const int t = c4*4;
        float4 v = {0.f,0.f,0.f,0.f}, wv = {0.f,0.f,0.f,0.f};
        if (nn < N && t < TT)
            v = *reinterpret_cast<const float4*>(a + (size_t)nn*TT + t);
        curv[q] = v; delv[q] = wv;
    }

    for (int t0 = 0; t0 < TT; t0 += 32) {
#pragma unroll
        for (int q = 0; q < 8; q++) {
            const int flat = q*128 + tid;
            const int row = flat >> 3, c4 = flat & 7;
            *reinterpret_cast<float4*>(&sx[row][c4*4]) = curv[q];
            *reinterpret_cast<float4*>(&sd[row][c4*4]) = delv[q];
        }
        __syncthreads();

        const int t0n = t0 + 32;
        if (t0n < TT) {
#pragma unroll
            for (int q = 0; q < 8; q++) {
                const int flat = q*128 + tid;
                const int row = flat >> 3, c4 = flat & 7;
                const int nn = n0 + row;
                const int t = t0n + c4*4;
                float4 v = {0.f,0.f,0.f,0.f}, wv = {0.f,0.f,0.f,0.f};
                if (nn < N) {
                    if (t < TT)
                        v = *reinterpret_cast<const float4*>(a + (size_t)nn*TT + t);
                    const int td = t - 100;
                    if (td >= 0 && td < TT)
                        wv = *reinterpret_cast<const float4*>(a + (size_t)nn*TT + td);
                }
                curv[q] = v; delv[q] = wv;
            }
        }

        if (n < N) {
            const int tmax = min(32, TT - t0);    // 32 or 12, both /4
            for (int tq = 0; tq < tmax; tq += 4) {
                float4 X  = *reinterpret_cast<const float4*>(&sx[tid][tq]);
                float4 XD = *reinterpret_cast<const float4*>(&sd[tid][tq]);
                float sp[4];
#pragma unroll
                for (int h = 0; h < 2; h++) {
                    const float x0  = (h == 0) ? X.x  : X.z;
                    const float x1  = (h == 0) ? X.y  : X.w;
                    const float xd0 = (h == 0) ? XD.x : XD.z;
                    const float xd1 = (h == 0) ? XD.y : XD.w;

                    // dx0 = d (x) x0, exact product
                    float ph = DD_H * x0;
                    float pl = fmaf(DD_H, x0, -ph);
                    pl = fmaf(DD_L, x0, pl);
                    // Z_{t+2} = d^2 Z + 2 d^2 P + dx0
                    df A = df_mulc(Z, D2_H, D2_L);
                    df B = df_mulc(P, TD2_H, TD2_L);
                    df Znew = df_add(df_add(A, B), df{ph, pl});
                    // P_{t+2} = d^2 P + dx0 + x1
                    df Cv = df_mulc(P, D2_H, D2_L);
                    df Pnew = df_addf(df_add(Cv, df{ph, pl}), x1);

                    // tail step 0 + y0 (y0 = CC1*d*(Z+P) - tail0) + spike
                    Z2t = DD_H * (Z2t + P2t);
                    P2t = fmaf(DD_H, P2t, xd0);
                    float tail0 = fmaf(CC2_H, P2t, fmaf(CC3_H, Z2t, CC2_L * P2t));
                    float sh = (Z.h + P.h) + (Z.l + P.l);
                    float y0 = fmaf(CC1D_H, sh, fmaf(CC1D_L, sh, -tail0));
                    float u0 = y0 + r;
                    float s0 = (u0 >= 10.0f) ? 1.0f : 0.0f;
                    r = 0.36787944117144233f * (r - 20.0f * s0);

                    // tail step 1 + y1 (y1 = CC1*Znew - tail1) + spike
                    Z2t = DD_H * (Z2t + P2t);
                    P2t = fmaf(DD_H, P2t, xd1);
                    float tail1 = fmaf(CC2_H, P2t, fmaf(CC3_H, Z2t, CC2_L * P2t));
                    float zh = Znew.h + Znew.l;
                    float y1 = fmaf(CC1_H, zh, fmaf(CC1_L, zh, -tail1));
                    float u1 = y1 + r;
                    float s1 = (u1 >= 10.0f) ? 1.0f : 0.0f;
                    r = 0.36787944117144233f * (r - 20.0f * s1);

                    Z = Znew; P = Pnew;
                    sp[h*2+0] = s0; sp[h*2+1] = s1;
                }
                float4 SP = {sp[0], sp[1], sp[2], sp[3]};
                *reinterpret_cast<float4*>(&sx[tid][tq]) = SP;
            }
        }
        __syncthreads();

        if (POOLW == 0) {
            // ---- plain cooperative float4 spike write-out ----
#pragma unroll
            for (int q = 0; q < 8; q++) {
                const int flat = q*128 + tid;
                const int row = flat >> 3, c4 = flat & 7;
                const int nn = n0 + row;
                const int t = t0 + c4*4;
                if (nn < N && t < TT)
                    *reinterpret_cast<float4*>(s + (size_t)nn*TT + t) =
                        *reinterpret_cast<const float4*>(&sx[row][c4*4]);
            }
        } else {
            // ---- fused 2x2 sum-pool: 32 pooled neurons/block, 11*sum exact ----
            constexpr int HALF = POOLW/2;
#pragma unroll
            for (int q = 0; q < 2; q++) {
                const int item = q*128 + tid;
                const int p = item >> 3, c4 = item & 7;
                const int t = t0 + c4*4;
                if (t < TT) {
                    const int hp = p / HALF, wo = p % HALF;
                    const int r00 = 2*hp*POOLW + 2*wo;
                    float4 v00 = *reinterpret_cast<const float4*>(&sx[r00][c4*4]);
                    float4 v01 = *reinterpret_cast<const float4*>(&sx[r00+1][c4*4]);
                    float4 v10 = *reinterpret_cast<const float4*>(&sx[r00+POOLW][c4*4]);
                    float4 v11 = *reinterpret_cast<const float4*>(&sx[r00+POOLW+1][c4*4]);
                    float4 o;
                    o.x = 11.0f * (v00.x + v01.x + v10.x + v11.x);
                    o.y = 11.0f * (v00.y + v01.y + v10.y + v11.y);
                    o.z = 11.0f * (v00.z + v01.z + v10.z + v11.z);
                    o.w = 11.0f * (v00.w + v01.w + v10.w + v11.w);
                    *reinterpret_cast<float4*>(s + (size_t)(n0/4 + p)*TT + t) = o;
                }
            }
        }
        __syncthreads();   // smem reused next tile
    }
}

// =====================================================================
// Dense readout, split-K x4: up[z][b][o][t] = sum_{i in chunk z} s5 * Wf
// s5 binary -> products exact; TwoSum-compensated fp32 chunk sums.
// =====================================================================
__global__ void __launch_bounds__(320)
dense_partial_kernel(const float* __restrict__ s5, const float* __restrict__ wf,
                     float* __restrict__ up)
{
    __shared__ float wrow[1024];
    const int b = blockIdx.x, o = blockIdx.y, z = blockIdx.z;
    const int tid = threadIdx.x;
    for (int i = tid; i < 1024; i += 320) wrow[i] = wf[o*4096 + z*1024 + i];
    __syncthreads();
    if (tid >= TT) return;

    const float* p = s5 + (size_t)b * 4096 * TT + (size_t)z * 1024 * TT;
    float acc = 0.f, comp = 0.f;
    for (int i = 0; i < 1024; i++) {
        const float pr = wrow[i] * p[i*TT + tid];   // exact (x in {0,1})
        float sm = acc + pr;
        float bb = sm - acc;
        comp += (acc - (sm - bb)) + (pr - bb);
        acc = sm;
    }
    up[(size_t)z*48000 + (b*10 + o)*TT + tid] = acc + comp;
}

__global__ void dense_combine_kernel(const float* __restrict__ up, float* __restrict__ u)
{
    const int i = blockIdx.x*256 + threadIdx.x;
    if (i >= 48000) return;
    u[i] = ((up[i] + up[48000 + i]) + up[96000 + i]) + up[144000 + i];
}

// =====================================================================
extern "C" void kernel_launch(void* const* d_in, const int* in_sizes, int n_in,
                              void* d_out, int out_size)
{
    const float *s_in = nullptr, *W1 = nullptr, *W2 = nullptr, *W3 = nullptr, *Wf = nullptr;
    for (int i = 0; i < n_in; i++) {
        switch (in_sizes[i]) {
            case 11097600: s_in = (const float*)d_in[i]; break;   // [16,2,34,34,300]
            case 800:      W1   = (const float*)d_in[i]; break;   // [16,2,5,5]
            case 4608:     W2   = (const float*)d_in[i]; break;   // [32,16,3,3]
            case 18432:    W3   = (const float*)d_in[i]; break;   // [64,32,3,3]
            case 40960:    Wf   = (const float*)d_in[i]; break;   // [10,64,8,8]
        }
    }

    float *a, *sA, *sB, *u, *up;
    cudaGetSymbolAddress((void**)&a,  g_a);
    cudaGetSymbolAddress((void**)&sA, g_sA);
    cudaGetSymbolAddress((void**)&sB, g_sB);
    cudaGetSymbolAddress((void**)&u,  g_u);
    cudaGetSymbolAddress((void**)&up, g_up);

    // L1: conv 5x5 pad1  [16,2,34,34] -> [16,16,32,32]  (CO_T=16, one group)
    conv_kernel<2,2,16,16,5,5,34,34,32,32,1><<<dim3(32,32,16),160>>>(s_in, W1, a);
    // psp+spike+POOL fused: 262144 neurons -> pooled 65536 into sA
    psp_spike_kernel<32><<<2048,128>>>(a, sA, 262144);
    // s2 spikes
    psp_spike_kernel<0><<<512,128>>>(sA, sB, 65536);

    // L3: conv 3x3 pad1 [16,16,16,16] -> [16,32,16,16]  (CO_T=16: two groups)
    conv_kernel<16,2,16,32,3,3,16,16,16,16,1><<<dim3(16,16,32),160>>>(sB, W2, a);
    // psp+spike+POOL fused: 131072 -> pooled 32768 into sA
    psp_spike_kernel<16><<<1024,128>>>(a, sA, 131072);
    // s4 spikes
    psp_spike_kernel<0><<<256,128>>>(sA, sB, 32768);

    // L5: conv 3x3 pad1 [16,32,8,8] -> [16,64,8,8]  (CO_T=16: four groups)
    conv_kernel<32,2,16,64,3,3,8,8,8,8,1><<<dim3(8,8,64),160>>>(sB, W3, a);
    // s5 spikes
    psp_spike_kernel<0><<<512,128>>>(a, sA, 65536);

    // dense readout (split-K x4) + combine + final psp/spike into d_out
    dense_partial_kernel<<<dim3(16,10,4),320>>>(sA, Wf, up);
    dense_combine_kernel<<<188,256>>>(up, u);
    psp_spike_kernel<0><<<2,128>>>(u, (float*)d_out, 160);
}

// round 16
// speedup vs baseline: 1.7560x; 1.7560x over previous
#include <cuda_runtime.h>

#define TT 300

// ---------------- static scratch (no allocations allowed) ----------------
__device__ float g_a [78643200];   // conv outputs (max: layer1, 16*16*32*32*300)
__device__ float g_sA[78643200];   // ping buffer
__device__ float g_sB[19660800];   // pong buffer
__device__ float g_u [48000];      // dense pre-psp output (combined)
__device__ float g_up[192000];     // dense split-K partials (4 x 48000)

// ---------------- double-float constant splits (compile-time folded) ------
constexpr double DDd   = 0.9048374180359595;     // exp(-0.1)
constexpr double D2d   = 0.8187307530779818;     // exp(-0.2)
constexpr double TD2d  = 1.6374615061559637;     // 2*exp(-0.2)
constexpr double CC1d  = 0.2718281828459045;     // e/10
constexpr double CC1Dd = CC1d * DDd;             // (e/10)*exp(-0.1)
constexpr double CC2d  = 1.2340980408667956e-3;  // 10*exp(-9)
constexpr double CC3d  = 1.2340980408667956e-5;  // 0.1*exp(-9)
constexpr float DD_H   = (float)DDd;
constexpr float DD_L   = (float)(DDd   - (double)DD_H);
constexpr float D2_H   = (float)D2d;
constexpr float D2_L   = (float)(D2d   - (double)D2_H);
constexpr float TD2_H  = (float)TD2d;
constexpr float TD2_L  = (float)(TD2d  - (double)TD2_H);
constexpr float CC1_H  = (float)CC1d;
constexpr float CC1_L  = (float)(CC1d  - (double)CC1_H);
constexpr float CC1D_H = (float)CC1Dd;
constexpr float CC1D_L = (float)(CC1Dd - (double)CC1D_H);
constexpr float CC2_H  = (float)CC2d;
constexpr float CC2_L  = (float)(CC2d  - (double)CC2_H);
constexpr float CC3_H  = (float)CC3d;

// ---------------- double-float (two-float) primitives ---------------------
struct df { float h, l; };

__device__ __forceinline__ df df_add(df a, df b) {
    float s  = a.h + b.h;
    float bb = s - a.h;
    float e  = (a.h - (s - bb)) + (b.h - bb);
    e += a.l + b.l;
    float h = s + e;
    float l = e - (h - s);
    return {h, l};
}
__device__ __forceinline__ df df_addf(df a, float b) {
    float s  = a.h + b;
    float bb = s - a.h;
    float e  = (a.h - (s - bb)) + (b - bb);
    e += a.l;
    float h = s + e;
    float l = e - (h - s);
    return {h, l};
}
__device__ __forceinline__ df df_mulc(df a, float ch, float cl) {
    float p = a.h * ch;
    float e = fmaf(a.h, ch, -p);
    e = fmaf(a.h, cl, e);
    e = fmaf(a.l, ch, e);
    float h = p + e;
    float l = e - (h - p);
    return {h, l};
}

// ---------------- packed f32x2 primitives (sm_103a) ------------------------
// FFMA2 = two independent IEEE fp32 FMAs in one instruction. Pairing is along
// CO (each co keeps its own scalar chain) -> arithmetic BIT-IDENTICAL to the
// scalar version; only the instruction count halves.
__device__ __forceinline__ unsigned long long splat2(float x) {
    unsigned long long r;
    asm("mov.b64 %0, {%1, %1};" : "=l"(r) : "f"(x));
    return r;
}
__device__ __forceinline__ void ffma2(unsigned long long& acc,
                                      unsigned long long w,
                                      unsigned long long x) {
    asm("fma.rn.f32x2 %0, %1, %2, %0;" : "+l"(acc) : "l"(w), "l"(x));
}
__device__ __forceinline__ void unpack2(unsigned long long p, float& lo, float& hi) {
    asm("mov.b64 {%0, %1}, %2;" : "=f"(lo), "=f"(hi) : "l"(p));
}

// =====================================================================
// Spatial conv: t-coarsened x2 + NL=2 lane-split (R12/R14 numerics,
// bit-identical chains) with FFMA2 packed along CO pairs:
// per (ci,k) item: 1 LDG.64 + 2 splat-movs + CO_T/4 LDS.128 + CO_T/2*2 FFMA2
// = 23 instr per 32 scalar FMAs (was 37) -> 1.6x fewer issue slots.
// threads = 160 (2 t each); z = b + 16*co_group.
// =====================================================================
template<int CI,int NL,int CO_T,int CO_FULL,int KH,int KW,int HIN,int WIN,int HOUT,int WOUT,int PAD>
__global__ void __launch_bounds__(160, 3)
conv_kernel(const float* __restrict__ in, const float* __restrict__ w,
            float* __restrict__ out)
{
    __shared__ __align__(16) float sw[CI*KH*KW*CO_T];
    const int tid = threadIdx.x;
    const int ow = blockIdx.x, oh = blockIdx.y;
    const int b = blockIdx.z & 15;
    const int co_base = (blockIdx.z >> 4) * CO_T;

    for (int i = tid; i < CI*KH*KW*CO_T; i += 160) {
        int k = i / CO_T, co = i % CO_T;
        sw[i] = w[(co_base + co)*(CI*KH*KW) + k];
    }
    __syncthreads();

    const int t = tid * 2;
    if (t >= TT) return;

    // accP[lane][t][pair]: packed f32x2 accumulators (per-co scalar chains)
    unsigned long long accP[NL][2][CO_T/2];
#pragma unroll
    for (int l = 0; l < NL; l++)
#pragma unroll
        for (int h = 0; h < 2; h++)
#pragma unroll
            for (int p = 0; p < CO_T/2; p++) accP[l][h][p] = 0ull;

    for (int g = 0; g < CI/NL; g++) {
#pragma unroll
        for (int l = 0; l < NL; l++) {
            const int ci = g*NL + l;
            // ---- batched float2 load phase for this (g,l) ----
            float2 xv[KH*KW];
#pragma unroll
            for (int kh = 0; kh < KH; kh++) {
                const int ih = oh + kh - PAD;
#pragma unroll
                for (int kw = 0; kw < KW; kw++) {
                    const int iw = ow + kw - PAD;
                    const bool valid = ((unsigned)ih < (unsigned)HIN) && ((unsigned)iw < (unsigned)WIN);
                    float2 v = {0.f, 0.f};
                    if (valid)
                        v = *reinterpret_cast<const float2*>(
                                in + ((((b*CI + ci)*HIN + ih)*WIN) + iw)*TT + t);
                    xv[kh*KW + kw] = v;
                }
            }
            // ---- FFMA2 burst ----
#pragma unroll
            for (int k = 0; k < KH*KW; k++) {
                const unsigned long long x0p = splat2(xv[k].x);
                const unsigned long long x1p = splat2(xv[k].y);
                const ulonglong2* wv =
                    reinterpret_cast<const ulonglong2*>(&sw[(ci*KH*KW + k)*CO_T]);
#pragma unroll
                for (int p4 = 0; p4 < CO_T/4; p4++) {
                    ulonglong2 wq = wv[p4];            // LDS.128 = 2 packed pairs
                    ffma2(accP[l][0][p4*2+0], wq.x, x0p);
                    ffma2(accP[l][1][p4*2+0], wq.x, x1p);
                    ffma2(accP[l][0][p4*2+1], wq.y, x0p);
                    ffma2(accP[l][1][p4*2+1], wq.y, x1p);
                }
            }
        }
    }

    // unpack + exact Neumaier combine across lanes (same order as R12/R14)
#pragma unroll
    for (int p = 0; p < CO_T/2; p++) {
        float a0_0, a0_1, b0_0, b0_1;   // lane0/lane1, t0, co pair
        float a1_0, a1_1, b1_0, b1_1;   // t1
        unpack2(accP[0][0][p], a0_0, a0_1);
        unpack2(accP[1][0][p], b0_0, b0_1);
        unpack2(accP[0][1][p], a1_0, a1_1);
        unpack2(accP[1][1][p], b1_0, b1_1);

        float r00, r01, r10, r11;
        {   // co = 2p, t0
            float tv = a0_0 + b0_0; float bb = tv - a0_0;
            r00 = tv + ((a0_0 - (tv - bb)) + (b0_0 - bb));
        }
        {   // co = 2p, t1
            float tv = a1_0 + b1_0; float bb = tv - a1_0;
            r10 = tv + ((a1_0 - (tv - bb)) + (b1_0 - bb));
        }
        {   // co = 2p+1, t0
            float tv = a0_1 + b0_1; float bb = tv - a0_1;
            r01 = tv + ((a0_1 - (tv - bb)) + (b0_1 - bb));
        }
        {   // co = 2p+1, t1
            float tv = a1_1 + b1_1; float bb = tv - a1_1;
            r11 = tv + ((a1_1 - (tv - bb)) + (b1_1 - bb));
        }
        float* q0 = out + ((((b*CO_FULL) + (co_base + 2*p  ))*HOUT + oh)*WOUT + ow)*TT + t;
        float* q1 = out + ((((b*CO_FULL) + (co_base + 2*p+1))*HOUT + oh)*WOUT + ow)*TT + t;
        *reinterpret_cast<float2*>(q0) = make_float2(r00, r10);
        *reinterpret_cast<float2*>(q1) = make_float2(r01, r11);
    }
}

// =====================================================================
// PSP (2-step-blocked double-float IIR + fp32 delayed-tail IIR) fused with
// the bit-exact refractory scan, and (POOLW>0) the SLAYER 2x2 sum-pool
// (11 * sum of 4 binary spikes — exact in fp32, any order).
// POOLW = spatial row width (32 or 16); POOLW=0 -> plain spike output.
// 128 neurons/block; 32-t tiles; float4 staged I/O; next-tile prefetch.
// =====================================================================
template<int POOLW>
__global__ void __launch_bounds__(128)
psp_spike_kernel(const float* __restrict__ a, float* __restrict__ s, int N)
{
    __shared__ __align__(16) float sx[128][36];   // current tile (spikes in-place)
    __shared__ __align__(16) float sd[128][36];   // 100-delayed tile
    const int tid = threadIdx.x;
    const int n0 = blockIdx.x * 128;
    const int n  = n0 + tid;

    df Z = {0.f, 0.f}, P = {0.f, 0.f};
    float Z2t = 0.f, P2t = 0.f;
    float r   = 0.f;

    float4 curv[8], delv[8];

    // ---- prefetch tile 0 ----
#pragma unroll
    for (int q = 0; q < 8; q++) {
        const int flat = q*128 + tid;
        const int row = flat >> 3, c4 = flat & 7;
        const int nn = n0 + row;
        const int t = c4*4;
        float4 v = {0.f,0.f,0.f,0.f}, wv = {0.f,0.f,0.f,0.f};
        if (nn < N && t < TT)
            v = *reinterpret_cast<const float4*>(a + (size_t)nn*TT + t);
        curv[q] = v; delv[q] = wv;
    }

    for (int t0 = 0; t0 < TT; t0 += 32) {
#pragma unroll
        for (int q = 0; q < 8; q++) {
            const int flat = q*128 + tid;
            const int row = flat >> 3, c4 = flat & 7;
            *reinterpret_cast<float4*>(&sx[row][c4*4]) = curv[q];
            *reinterpret_cast<float4*>(&sd[row][c4*4]) = delv[q];
        }
        __syncthreads();

        const int t0n = t0 + 32;
        if (t0n < TT) {
#pragma unroll
            for (int q = 0; q < 8; q++) {
                const int flat = q*128 + tid;
                const int row = flat >> 3, c4 = flat & 7;
                const int nn = n0 + row;
                const int t = t0n + c4*4;
                float4 v = {0.f,0.f,0.f,0.f}, wv = {0.f,0.f,0.f,0.f};
                if (nn < N) {
                    if (t < TT)
                        v = *reinterpret_cast<const float4*>(a + (size_t)nn*TT + t);
                    const int td = t - 100;
                    if (td >= 0 && td < TT)
                        wv = *reinterpret_cast<const float4*>(a + (size_t)nn*TT + td);
                }
                curv[q] = v; delv[q] = wv;
            }
        }

        if (n < N) {
            const int tmax = min(32, TT - t0);    // 32 or 12, both /4
            for (int tq = 0; tq < tmax; tq += 4) {
                float4 X  = *reinterpret_cast<const float4*>(&sx[tid][tq]);
                float4 XD = *reinterpret_cast<const float4*>(&sd[tid][tq]);
                float sp[4];
#pragma unroll
                for (int h = 0; h < 2; h++) {
                    const float x0  = (h == 0) ? X.x  : X.z;
                    const float x1  = (h == 0) ? X.y  : X.w;
                    const float xd0 = (h == 0) ? XD.x : XD.z;
                    const float xd1 = (h == 0) ? XD.y : XD.w;

                    // dx0 = d (x) x0, exact product
                    float ph = DD_H * x0;
                    float pl = fmaf(DD_H, x0, -ph);
                    pl = fmaf(DD_L, x0, pl);
                    // Z_{t+2} = d^2 Z + 2 d^2 P + dx0
                    df A = df_mulc(Z, D2_H, D2_L);
                    df B = df_mulc(P, TD2_H, TD2_L);
                    df Znew = df_add(df_add(A, B), df{ph, pl});
                    // P_{t+2} = d^2 P + dx0 + x1
                    df Cv = df_mulc(P, D2_H, D2_L);
                    df Pnew = df_addf(df_add(Cv, df{ph, pl}), x1);

                    // tail step 0 + y0 (y0 = CC1*d*(Z+P) - tail0) + spike
                    Z2t = DD_H * (Z2t + P2t);
                    P2t = fmaf(DD_H, P2t, xd0);
                    float tail0 = fmaf(CC2_H, P2t, fmaf(CC3_H, Z2t, CC2_L * P2t));
                    float sh = (Z.h + P.h) + (Z.l + P.l);
                    float y0 = fmaf(CC1D_H, sh, fmaf(CC1D_L, sh, -tail0));
                    float u0 = y0 + r;
                    float s0 = (u0 >= 10.0f) ? 1.0f : 0.0f;
                    r = 0.36787944117144233f * (r - 20.0f * s0);

                    // tail step 1 + y1 (y1 = CC1*Znew - tail1) + spike
                    Z2t = DD_H * (Z2t + P2t);
                    P2t = fmaf(DD_H, P2t, xd1);
                    float tail1 = fmaf(CC2_H, P2t, fmaf(CC3_H, Z2t, CC2_L * P2t));
                    float zh = Znew.h + Znew.l;
                    float y1 = fmaf(CC1_H, zh, fmaf(CC1_L, zh, -tail1));
                    float u1 = y1 + r;
                    float s1 = (u1 >= 10.0f) ? 1.0f : 0.0f;
                    r = 0.36787944117144233f * (r - 20.0f * s1);

                    Z = Znew; P = Pnew;
                    sp[h*2+0] = s0; sp[h*2+1] = s1;
                }
                float4 SP = {sp[0], sp[1], sp[2], sp[3]};
                *reinterpret_cast<float4*>(&sx[tid][tq]) = SP;
            }
        }
        __syncthreads();

        if (POOLW == 0) {
            // ---- plain cooperative float4 spike write-out ----
#pragma unroll
            for (int q = 0; q < 8; q++) {
                const int flat = q*128 + tid;
                const int row = flat >> 3, c4 = flat & 7;
                const int nn = n0 + row;
                const int t = t0 + c4*4;
                if (nn < N && t < TT)
                    *reinterpret_cast<float4*>(s + (size_t)nn*TT + t) =
                        *reinterpret_cast<const float4*>(&sx[row][c4*4]);
            }
        } else {
            // ---- fused 2x2 sum-pool: 32 pooled neurons/block, 11*sum exact ----
            constexpr int HALF = POOLW/2;
#pragma unroll
            for (int q = 0; q < 2; q++) {
                const int item = q*128 + tid;
                const int p = item >> 3, c4 = item & 7;
                const int t = t0 + c4*4;
                if (t < TT) {
                    const int hp = p / HALF, wo = p % HALF;
                    const int r00 = 2*hp*POOLW + 2*wo;
                    float4 v00 = *reinterpret_cast<const float4*>(&sx[r00][c4*4]);
                    float4 v01 = *reinterpret_cast<const float4*>(&sx[r00+1][c4*4]);
                    float4 v10 = *reinterpret_cast<const float4*>(&sx[r00+POOLW][c4*4]);
                    float4 v11 = *reinterpret_cast<const float4*>(&sx[r00+POOLW+1][c4*4]);
                    float4 o;
                    o.x = 11.0f * (v00.x + v01.x + v10.x + v11.x);
                    o.y = 11.0f * (v00.y + v01.y + v10.y + v11.y);
                    o.z = 11.0f * (v00.z + v01.z + v10.z + v11.z);
                    o.w = 11.0f * (v00.w + v01.w + v10.w + v11.w);
                    *reinterpret_cast<float4*>(s + (size_t)(n0/4 + p)*TT + t) = o;
                }
            }
        }
        __syncthreads();   // smem reused next tile
    }
}

// =====================================================================
// Dense readout, split-K x4: up[z][b][o][t] = sum_{i in chunk z} s5 * Wf
// s5 binary -> products exact; TwoSum-compensated fp32 chunk sums.
// =====================================================================
__global__ void __launch_bounds__(320)
dense_partial_kernel(const float* __restrict__ s5, const float* __restrict__ wf,
                     float* __restrict__ up)
{
    __shared__ float wrow[1024];
    const int b = blockIdx.x, o = blockIdx.y, z = blockIdx.z;
    const int tid = threadIdx.x;
    for (int i = tid; i < 1024; i += 320) wrow[i] = wf[o*4096 + z*1024 + i];
    __syncthreads();
    if (tid >= TT) return;

    const float* p = s5 + (size_t)b * 4096 * TT + (size_t)z * 1024 * TT;
    float acc = 0.f, comp = 0.f;
    for (int i = 0; i < 1024; i++) {
        const float pr = wrow[i] * p[i*TT + tid];   // exact (x in {0,1})
        float sm = acc + pr;
        float bb = sm - acc;
        comp += (acc - (sm - bb)) + (pr - bb);
        acc = sm;
    }
    up[(size_t)z*48000 + (b*10 + o)*TT + tid] = acc + comp;
}

__global__ void dense_combine_kernel(const float* __restrict__ up, float* __restrict__ u)
{
    const int i = blockIdx.x*256 + threadIdx.x;
    if (i >= 48000) return;
    u[i] = ((up[i] + up[48000 + i]) + up[96000 + i]) + up[144000 + i];
}

// =====================================================================
extern "C" void kernel_launch(void* const* d_in, const int* in_sizes, int n_in,
                              void* d_out, int out_size)
{
    const float *s_in = nullptr, *W1 = nullptr, *W2 = nullptr, *W3 = nullptr, *Wf = nullptr;
    for (int i = 0; i < n_in; i++) {
        switch (in_sizes[i]) {
            case 11097600: s_in = (const float*)d_in[i]; break;   // [16,2,34,34,300]
            case 800:      W1   = (const float*)d_in[i]; break;   // [16,2,5,5]
            case 4608:     W2   = (const float*)d_in[i]; break;   // [32,16,3,3]
            case 18432:    W3   = (const float*)d_in[i]; break;   // [64,32,3,3]
            case 40960:    Wf   = (const float*)d_in[i]; break;   // [10,64,8,8]
        }
    }

    float *a, *sA, *sB, *u, *up;
    cudaGetSymbolAddress((void**)&a,  g_a);
    cudaGetSymbolAddress((void**)&sA, g_sA);
    cudaGetSymbolAddress((void**)&sB, g_sB);
    cudaGetSymbolAddress((void**)&u,  g_u);
    cudaGetSymbolAddress((void**)&up, g_up);

    // L1: conv 5x5 pad1  [16,2,34,34] -> [16,16,32,32]  (CO_T=16, one group)
    conv_kernel<2,2,16,16,5,5,34,34,32,32,1><<<dim3(32,32,16),160>>>(s_in, W1, a);
    // psp+spike+POOL fused: 262144 neurons -> pooled 65536 into sA
    psp_spike_kernel<32><<<2048,128>>>(a, sA, 262144);
    // s2 spikes
    psp_spike_kernel<0><<<512,128>>>(sA, sB, 65536);

    // L3: conv 3x3 pad1 [16,16,16,16] -> [16,32,16,16]  (CO_T=16: two groups)
    conv_kernel<16,2,16,32,3,3,16,16,16,16,1><<<dim3(16,16,32),160>>>(sB, W2, a);
    // psp+spike+POOL fused: 131072 -> pooled 32768 into sA
    psp_spike_kernel<16><<<1024,128>>>(a, sA, 131072);
    // s4 spikes
    psp_spike_kernel<0><<<256,128>>>(sA, sB, 32768);

    // L5: conv 3x3 pad1 [16,32,8,8] -> [16,64,8,8]  (CO_T=16: four groups)
    conv_kernel<32,2,16,64,3,3,8,8,8,8,1><<<dim3(8,8,64),160>>>(sB, W3, a);
    // s5 spikes
    psp_spike_kernel<0><<<512,128>>>(a, sA, 65536);

    // dense readout (split-K x4) + combine + final psp/spike into d_out
    dense_partial_kernel<<<dim3(16,10,4),320>>>(sA, Wf, up);
    dense_combine_kernel<<<188,256>>>(up, u);
    psp_spike_kernel<0><<<2,128>>>(u, (float*)d_out, 160);
}

// round 17
// speedup vs baseline: 1.8124x; 1.0321x over previous
#include <cuda_runtime.h>

#define TT 300

// ---------------- static scratch (no allocations allowed) ----------------
__device__ float g_a [78643200];   // conv outputs (max: layer1, 16*16*32*32*300)
__device__ float g_sA[78643200];   // ping buffer
__device__ float g_sB[19660800];   // pong buffer
__device__ float g_u [48000];      // dense pre-psp output (combined)
__device__ float g_up[192000];     // dense split-K partials (4 x 48000)

// ---------------- double-float constant splits (compile-time folded) ------
constexpr double DDd   = 0.9048374180359595;     // exp(-0.1)
constexpr double D2d   = 0.8187307530779818;     // exp(-0.2)
constexpr double TD2d  = 1.6374615061559637;     // 2*exp(-0.2)
constexpr double CC1d  = 0.2718281828459045;     // e/10
constexpr double CC1Dd = CC1d * DDd;             // (e/10)*exp(-0.1)
constexpr double CC2d  = 1.2340980408667956e-3;  // 10*exp(-9)
constexpr double CC3d  = 1.2340980408667956e-5;  // 0.1*exp(-9)
constexpr float DD_H   = (float)DDd;
constexpr float DD_L   = (float)(DDd   - (double)DD_H);
constexpr float D2_H   = (float)D2d;
constexpr float D2_L   = (float)(D2d   - (double)D2_H);
constexpr float TD2_H  = (float)TD2d;
constexpr float TD2_L  = (float)(TD2d  - (double)TD2_H);
constexpr float CC1_H  = (float)CC1d;
constexpr float CC1_L  = (float)(CC1d  - (double)CC1_H);
constexpr float CC1D_H = (float)CC1Dd;
constexpr float CC1D_L = (float)(CC1Dd - (double)CC1D_H);
constexpr float CC2_H  = (float)CC2d;
constexpr float CC2_L  = (float)(CC2d  - (double)CC2_H);
constexpr float CC3_H  = (float)CC3d;

// ---------------- double-float (two-float) primitives ---------------------
struct df { float h, l; };

__device__ __forceinline__ df df_add(df a, df b) {
    float s  = a.h + b.h;
    float bb = s - a.h;
    float e  = (a.h - (s - bb)) + (b.h - bb);
    e += a.l + b.l;
    float h = s + e;
    float l = e - (h - s);
    return {h, l};
}
__device__ __forceinline__ df df_addf(df a, float b) {
    float s  = a.h + b;
    float bb = s - a.h;
    float e  = (a.h - (s - bb)) + (b - bb);
    e += a.l;
    float h = s + e;
    float l = e - (h - s);
    return {h, l};
}
__device__ __forceinline__ df df_mulc(df a, float ch, float cl) {
    float p = a.h * ch;
    float e = fmaf(a.h, ch, -p);
    e = fmaf(a.h, cl, e);
    e = fmaf(a.l, ch, e);
    float h = p + e;
    float l = e - (h - p);
    return {h, l};
}

// ---------------- packed f32x2 primitives (sm_103a) ------------------------
// FFMA2 = two independent IEEE fp32 FMAs in one instruction. Pairing is along
// CO (each co keeps its own scalar chain) -> arithmetic BIT-IDENTICAL to the
// scalar version; only the instruction count halves.
__device__ __forceinline__ unsigned long long splat2(float x) {
    unsigned long long r;
    asm("mov.b64 %0, {%1, %1};" : "=l"(r) : "f"(x));
    return r;
}
__device__ __forceinline__ void ffma2(unsigned long long& acc,
                                      unsigned long long w,
                                      unsigned long long x) {
    asm("fma.rn.f32x2 %0, %1, %2, %0;" : "+l"(acc) : "l"(w), "l"(x));
}
__device__ __forceinline__ void unpack2(unsigned long long p, float& lo, float& hi) {
    asm("mov.b64 {%0, %1}, %2;" : "=f"(lo), "=f"(hi) : "l"(p));
}
// exact 2-term Neumaier combine (identical to R12/R14/R16 combine step)
__device__ __forceinline__ float neum2(float a, float b) {
    float tv = a + b;
    float bb = tv - a;
    return tv + ((a - (tv - bb)) + (b - bb));
}

// =====================================================================
// 3x3 conv, t-COARSENED x4: thread handles 4 timesteps (LDG.128 in /
// STG.128 out), CO_T=8, 2 ow-columns per 160-thread block. Per (ci,k)
// item: 1 LDG.128 + 2 LDS.128 + 4 splat-movs + 16 FFMA2 -> LSU ops per
// 32 MACs drop 5 -> 3 (movs ride the idle ALU pipe). Numerics identical
// to R16: NL=2 ci-parity lane chains, (ci asc, kh, kw) order per lane,
// exact Neumaier lane combine.
// z = b + 16*co_group.
// =====================================================================
template<int CI,int CO_T,int CO_FULL,int HIN,int WIN,int HOUT,int WOUT>
__global__ void __launch_bounds__(160, 3)
conv3_kernel(const float* __restrict__ in, const float* __restrict__ w,
             float* __restrict__ out)
{
    __shared__ __align__(16) float sw[CI*9*CO_T];
    const int tid = threadIdx.x;
    const int oh = blockIdx.y;
    const int b = blockIdx.z & 15;
    const int co_base = (blockIdx.z >> 4) * CO_T;

    for (int i = tid; i < CI*9*CO_T; i += 160) {
        int k = i / CO_T, co = i % CO_T;
        sw[i] = w[(co_base + co)*(CI*9) + k];
    }
    __syncthreads();

    const int sub = tid / 80;                 // which ow column
    const int t   = (tid % 80) * 4;
    const int ow  = blockIdx.x * 2 + sub;
    if (t >= TT) return;

    // accP[lane][t][co_pair]: packed f32x2 accumulators (per-co scalar chains)
    unsigned long long accP[2][4][CO_T/2];
#pragma unroll
    for (int l = 0; l < 2; l++)
#pragma unroll
        for (int tq = 0; tq < 4; tq++)
#pragma unroll
            for (int p = 0; p < CO_T/2; p++) accP[l][tq][p] = 0ull;

    for (int g = 0; g < CI/2; g++) {
#pragma unroll
        for (int l = 0; l < 2; l++) {
            const int ci = g*2 + l;
            // ---- batched float4 load phase ----
            float4 xv[9];
#pragma unroll
            for (int kh = 0; kh < 3; kh++) {
                const int ih = oh + kh - 1;
#pragma unroll
                for (int kw = 0; kw < 3; kw++) {
                    const int iw = ow + kw - 1;
                    const bool valid = ((unsigned)ih < (unsigned)HIN) && ((unsigned)iw < (unsigned)WIN);
                    float4 v = {0.f, 0.f, 0.f, 0.f};
                    if (valid)
                        v = *reinterpret_cast<const float4*>(
                                in + ((((b*CI + ci)*HIN + ih)*WIN) + iw)*TT + t);
                    xv[kh*3 + kw] = v;
                }
            }
            // ---- FFMA2 burst ----
#pragma unroll
            for (int k = 0; k < 9; k++) {
                unsigned long long xs[4];
                xs[0] = splat2(xv[k].x);
                xs[1] = splat2(xv[k].y);
                xs[2] = splat2(xv[k].z);
                xs[3] = splat2(xv[k].w);
                const ulonglong2* wv =
                    reinterpret_cast<const ulonglong2*>(&sw[(ci*9 + k)*CO_T]);
#pragma unroll
                for (int p4 = 0; p4 < CO_T/4; p4++) {
                    ulonglong2 wq = wv[p4];        // LDS.128 = 2 packed co-pairs
#pragma unroll
                    for (int tq = 0; tq < 4; tq++) {
                        ffma2(accP[l][tq][p4*2+0], wq.x, xs[tq]);
                        ffma2(accP[l][tq][p4*2+1], wq.y, xs[tq]);
                    }
                }
            }
        }
    }

    // unpack + exact Neumaier combine across lanes, float4 stores
#pragma unroll
    for (int p = 0; p < CO_T/2; p++) {
        float4 r_even, r_odd;
        float* re = &r_even.x;
        float* ro = &r_odd.x;
#pragma unroll
        for (int tq = 0; tq < 4; tq++) {
            float a_lo, a_hi, b_lo, b_hi;
            unpack2(accP[0][tq][p], a_lo, a_hi);
            unpack2(accP[1][tq][p], b_lo, b_hi);
            re[tq] = neum2(a_lo, b_lo);
            ro[tq] = neum2(a_hi, b_hi);
        }
        float* q0 = out + ((((b*CO_FULL) + (co_base + 2*p  ))*HOUT + oh)*WOUT + ow)*TT + t;
        float* q1 = out + ((((b*CO_FULL) + (co_base + 2*p+1))*HOUT + oh)*WOUT + ow)*TT + t;
        *reinterpret_cast<float4*>(q0) = r_even;
        *reinterpret_cast<float4*>(q1) = r_odd;
    }
}

// =====================================================================
// L1 conv (5x5): R16 kernel unchanged (t x2, CO_T=16, NL=2, FFMA2 along CO)
// =====================================================================
template<int CI,int NL,int CO_T,int CO_FULL,int KH,int KW,int HIN,int WIN,int HOUT,int WOUT,int PAD>
__global__ void __launch_bounds__(160, 3)
conv_kernel(const float* __restrict__ in, const float* __restrict__ w,
            float* __restrict__ out)
{
    __shared__ __align__(16) float sw[CI*KH*KW*CO_T];
    const int tid = threadIdx.x;
    const int ow = blockIdx.x, oh = blockIdx.y;
    const int b = blockIdx.z & 15;
    const int co_base = (blockIdx.z >> 4) * CO_T;

    for (int i = tid; i < CI*KH*KW*CO_T; i += 160) {
        int k = i / CO_T, co = i % CO_T;
        sw[i] = w[(co_base + co)*(CI*KH*KW) + k];
    }
    __syncthreads();

    const int t = tid * 2;
    if (t >= TT) return;

    unsigned long long accP[NL][2][CO_T/2];
#pragma unroll
    for (int l = 0; l < NL; l++)
#pragma unroll
        for (int h = 0; h < 2; h++)
#pragma unroll
            for (int p = 0; p < CO_T/2; p++) accP[l][h][p] = 0ull;

    for (int g = 0; g < CI/NL; g++) {
#pragma unroll
        for (int l = 0; l < NL; l++) {
            const int ci = g*NL + l;
            float2 xv[KH*KW];
#pragma unroll
            for (int kh = 0; kh < KH; kh++) {
                const int ih = oh + kh - PAD;
#pragma unroll
                for (int kw = 0; kw < KW; kw++) {
                    const int iw = ow + kw - PAD;
                    const bool valid = ((unsigned)ih < (unsigned)HIN) && ((unsigned)iw < (unsigned)WIN);
                    float2 v = {0.f, 0.f};
                    if (valid)
                        v = *reinterpret_cast<const float2*>(
                                in + ((((b*CI + ci)*HIN + ih)*WIN) + iw)*TT + t);
                    xv[kh*KW + kw] = v;
                }
            }
#pragma unroll
            for (int k = 0; k < KH*KW; k++) {
                const unsigned long long x0p = splat2(xv[k].x);
                const unsigned long long x1p = splat2(xv[k].y);
                const ulonglong2* wv =
                    reinterpret_cast<const ulonglong2*>(&sw[(ci*KH*KW + k)*CO_T]);
#pragma unroll
                for (int p4 = 0; p4 < CO_T/4; p4++) {
                    ulonglong2 wq = wv[p4];
                    ffma2(accP[l][0][p4*2+0], wq.x, x0p);
                    ffma2(accP[l][1][p4*2+0], wq.x, x1p);
                    ffma2(accP[l][0][p4*2+1], wq.y, x0p);
                    ffma2(accP[l][1][p4*2+1], wq.y, x1p);
                }
            }
        }
    }

#pragma unroll
    for (int p = 0; p < CO_T/2; p++) {
        float a0_0, a0_1, b0_0, b0_1;
        float a1_0, a1_1, b1_0, b1_1;
        unpack2(accP[0][0][p], a0_0, a0_1);
        unpack2(accP[1][0][p], b0_0, b0_1);
        unpack2(accP[0][1][p], a1_0, a1_1);
        unpack2(accP[1][1][p], b1_0, b1_1);
        float r00 = neum2(a0_0, b0_0);
        float r10 = neum2(a1_0, b1_0);
        float r01 = neum2(a0_1, b0_1);
        float r11 = neum2(a1_1, b1_1);
        float* q0 = out + ((((b*CO_FULL) + (co_base + 2*p  ))*HOUT + oh)*WOUT + ow)*TT + t;
        float* q1 = out + ((((b*CO_FULL) + (co_base + 2*p+1))*HOUT + oh)*WOUT + ow)*TT + t;
        *reinterpret_cast<float2*>(q0) = make_float2(r00, r10);
        *reinterpret_cast<float2*>(q1) = make_float2(r01, r11);
    }
}

// =====================================================================
// PSP (2-step-blocked double-float IIR + fp32 delayed-tail IIR) fused with
// the bit-exact refractory scan, and (POOLW>0) the SLAYER 2x2 sum-pool
// (11 * sum of 4 binary spikes — exact in fp32, any order).
// POOLW = spatial row width (32 or 16); POOLW=0 -> plain spike output.
// 128 neurons/block; 32-t tiles; float4 staged I/O; next-tile prefetch.
// =====================================================================
template<int POOLW>
__global__ void __launch_bounds__(128)
psp_spike_kernel(const float* __restrict__ a, float* __restrict__ s, int N)
{
    __shared__ __align__(16) float sx[128][36];   // current tile (spikes in-place)
    __shared__ __align__(16) float sd[128][36];   // 100-delayed tile
    const int tid = threadIdx.x;
    const int n0 = blockIdx.x * 128;
    const int n  = n0 + tid;

    df Z = {0.f, 0.f}, P = {0.f, 0.f};
    float Z2t = 0.f, P2t = 0.f;
    float r   = 0.f;

    float4 curv[8], delv[8];

    // ---- prefetch tile 0 ----
#pragma unroll
    for (int q = 0; q < 8; q++) {
        const int flat = q*128 + tid;
        const int row = flat >> 3, c4 = flat & 7;
        const int nn = n0 + row;
        const int t = c4*4;
        float4 v = {0.f,0.f,0.f,0.f}, wv = {0.f,0.f,0.f,0.f};
        if (nn < N && t < TT)
            v = *reinterpret_cast<const float4*>(a + (size_t)nn*TT + t);
        curv[q] = v; delv[q] = wv;
    }

    for (int t0 = 0; t0 < TT; t0 += 32) {
#pragma unroll
        for (int q = 0; q < 8; q++) {
            const int flat = q*128 + tid;
            const int row = flat >> 3, c4 = flat & 7;
            *reinterpret_cast<float4*>(&sx[row][c4*4]) = curv[q];
            *reinterpret_cast<float4*>(&sd[row][c4*4]) = delv[q];
        }
        __syncthreads();

        const int t0n = t0 + 32;
        if (t0n < TT) {
#pragma unroll
            for (int q = 0; q < 8; q++) {
                const int flat = q*128 + tid;
                const int row = flat >> 3, c4 = flat & 7;
                const int nn = n0 + row;
                const int t = t0n + c4*4;
                float4 v = {0.f,0.f,0.f,0.f}, wv = {0.f,0.f,0.f,0.f};
                if (nn < N) {
                    if (t < TT)
                        v = *reinterpret_cast<const float4*>(a + (size_t)nn*TT + t);
                    const int td = t - 100;
                    if (td >= 0 && td < TT)
                        wv = *reinterpret_cast<const float4*>(a + (size_t)nn*TT + td);
                }
                curv[q] = v; delv[q] = wv;
            }
        }

        if (n < N) {
            const int tmax = min(32, TT - t0);    // 32 or 12, both /4
            for (int tq = 0; tq < tmax; tq += 4) {
                float4 X  = *reinterpret_cast<const float4*>(&sx[tid][tq]);
                float4 XD = *reinterpret_cast<const float4*>(&sd[tid][tq]);
                float sp[4];
#pragma unroll
                for (int h = 0; h < 2; h++) {
                    const float x0  = (h == 0) ? X.x  : X.z;
                    const float x1  = (h == 0) ? X.y  : X.w;
                    const float xd0 = (h == 0) ? XD.x : XD.z;
                    const float xd1 = (h == 0) ? XD.y : XD.w;

                    // dx0 = d (x) x0, exact product
                    float ph = DD_H * x0;
                    float pl = fmaf(DD_H, x0, -ph);
                    pl = fmaf(DD_L, x0, pl);
                    // Z_{t+2} = d^2 Z + 2 d^2 P + dx0
                    df A = df_mulc(Z, D2_H, D2_L);
                    df B = df_mulc(P, TD2_H, TD2_L);
                    df Znew = df_add(df_add(A, B), df{ph, pl});
                    // P_{t+2} = d^2 P + dx0 + x1
                    df Cv = df_mulc(P, D2_H, D2_L);
                    df Pnew = df_addf(df_add(Cv, df{ph, pl}), x1);

                    // tail step 0 + y0 (y0 = CC1*d*(Z+P) - tail0) + spike
                    Z2t = DD_H * (Z2t + P2t);
                    P2t = fmaf(DD_H, P2t, xd0);
                    float tail0 = fmaf(CC2_H, P2t, fmaf(CC3_H, Z2t, CC2_L * P2t));
                    float sh = (Z.h + P.h) + (Z.l + P.l);
                    float y0 = fmaf(CC1D_H, sh, fmaf(CC1D_L, sh, -tail0));
                    float u0 = y0 + r;
                    float s0 = (u0 >= 10.0f) ? 1.0f : 0.0f;
                    r = 0.36787944117144233f * (r - 20.0f * s0);

                    // tail step 1 + y1 (y1 = CC1*Znew - tail1) + spike
                    Z2t = DD_H * (Z2t + P2t);
                    P2t = fmaf(DD_H, P2t, xd1);
                    float tail1 = fmaf(CC2_H, P2t, fmaf(CC3_H, Z2t, CC2_L * P2t));
                    float zh = Znew.h + Znew.l;
                    float y1 = fmaf(CC1_H, zh, fmaf(CC1_L, zh, -tail1));
                    float u1 = y1 + r;
                    float s1 = (u1 >= 10.0f) ? 1.0f : 0.0f;
                    r = 0.36787944117144233f * (r - 20.0f * s1);

                    Z = Znew; P = Pnew;
                    sp[h*2+0] = s0; sp[h*2+1] = s1;
                }
                float4 SP = {sp[0], sp[1], sp[2], sp[3]};
                *reinterpret_cast<float4*>(&sx[tid][tq]) = SP;
            }
        }
        __syncthreads();

        if (POOLW == 0) {
            // ---- plain cooperative float4 spike write-out ----
#pragma unroll
            for (int q = 0; q < 8; q++) {
                const int flat = q*128 + tid;
                const int row = flat >> 3, c4 = flat & 7;
                const int nn = n0 + row;
                const int t = t0 + c4*4;
                if (nn < N && t < TT)
                    *reinterpret_cast<float4*>(s + (size_t)nn*TT + t) =
                        *reinterpret_cast<const float4*>(&sx[row][c4*4]);
            }
        } else {
            // ---- fused 2x2 sum-pool: 32 pooled neurons/block, 11*sum exact ----
            constexpr int HALF = POOLW/2;
#pragma unroll
            for (int q = 0; q < 2; q++) {
                const int item = q*128 + tid;
                const int p = item >> 3, c4 = item & 7;
                const int t = t0 + c4*4;
                if (t < TT) {
                    const int hp = p / HALF, wo = p % HALF;
                    const int r00 = 2*hp*POOLW + 2*wo;
                    float4 v00 = *reinterpret_cast<const float4*>(&sx[r00][c4*4]);
                    float4 v01 = *reinterpret_cast<const float4*>(&sx[r00+1][c4*4]);
                    float4 v10 = *reinterpret_cast<const float4*>(&sx[r00+POOLW][c4*4]);
                    float4 v11 = *reinterpret_cast<const float4*>(&sx[r00+POOLW+1][c4*4]);
                    float4 o;
                    o.x = 11.0f * (v00.x + v01.x + v10.x + v11.x);
                    o.y = 11.0f * (v00.y + v01.y + v10.y + v11.y);
                    o.z = 11.0f * (v00.z + v01.z + v10.z + v11.z);
                    o.w = 11.0f * (v00.w + v01.w + v10.w + v11.w);
                    *reinterpret_cast<float4*>(s + (size_t)(n0/4 + p)*TT + t) = o;
                }
            }
        }
        __syncthreads();   // smem reused next tile
    }
}

// =====================================================================
// Dense readout, split-K x4: up[z][b][o][t] = sum_{i in chunk z} s5 * Wf
// s5 binary -> products exact; TwoSum-compensated fp32 chunk sums.
// =====================================================================
__global__ void __launch_bounds__(320)
dense_partial_kernel(const float* __restrict__ s5, const float* __restrict__ wf,
                     float* __restrict__ up)
{
    __shared__ float wrow[1024];
    const int b = blockIdx.x, o = blockIdx.y, z = blockIdx.z;
    const int tid = threadIdx.x;
    for (int i = tid; i < 1024; i += 320) wrow[i] = wf[o*4096 + z*1024 + i];
    __syncthreads();
    if (tid >= TT) return;

    const float* p = s5 + (size_t)b * 4096 * TT + (size_t)z * 1024 * TT;
    float acc = 0.f, comp = 0.f;
    for (int i = 0; i < 1024; i++) {
        const float pr = wrow[i] * p[i*TT + tid];   // exact (x in {0,1})
        float sm = acc + pr;
        float bb = sm - acc;
        comp += (acc - (sm - bb)) + (pr - bb);
        acc = sm;
    }
    up[(size_t)z*48000 + (b*10 + o)*TT + tid] = acc + comp;
}

__global__ void dense_combine_kernel(const float* __restrict__ up, float* __restrict__ u)
{
    const int i = blockIdx.x*256 + threadIdx.x;
    if (i >= 48000) return;
    u[i] = ((up[i] + up[48000 + i]) + up[96000 + i]) + up[144000 + i];
}

// =====================================================================
extern "C" void kernel_launch(void* const* d_in, const int* in_sizes, int n_in,
                              void* d_out, int out_size)
{
    const float *s_in = nullptr, *W1 = nullptr, *W2 = nullptr, *W3 = nullptr, *Wf = nullptr;
    for (int i = 0; i < n_in; i++) {
        switch (in_sizes[i]) {
            case 11097600: s_in = (const float*)d_in[i]; break;   // [16,2,34,34,300]
            case 800:      W1   = (const float*)d_in[i]; break;   // [16,2,5,5]
            case 4608:     W2   = (const float*)d_in[i]; break;   // [32,16,3,3]
            case 18432:    W3   = (const float*)d_in[i]; break;   // [64,32,3,3]
            case 40960:    Wf   = (const float*)d_in[i]; break;   // [10,64,8,8]
        }
    }

    float *a, *sA, *sB, *u, *up;
    cudaGetSymbolAddress((void**)&a,  g_a);
    cudaGetSymbolAddress((void**)&sA, g_sA);
    cudaGetSymbolAddress((void**)&sB, g_sB);
    cudaGetSymbolAddress((void**)&u,  g_u);
    cudaGetSymbolAddress((void**)&up, g_up);

    // L1: conv 5x5 pad1  [16,2,34,34] -> [16,16,32,32]  (R16 kernel, CO_T=16)
    conv_kernel<2,2,16,16,5,5,34,34,32,32,1><<<dim3(32,32,16),160>>>(s_in, W1, a);
    // psp+spike+POOL fused: 262144 neurons -> pooled 65536 into sA
    psp_spike_kernel<32><<<2048,128>>>(a, sA, 262144);
    // s2 spikes
    psp_spike_kernel<0><<<512,128>>>(sA, sB, 65536);

    // L3: conv 3x3 pad1 [16,16,16,16] -> [16,32,16,16]  (t x4, CO_T=8: 4 groups)
    conv3_kernel<16,8,32,16,16,16,16><<<dim3(8,16,64),160>>>(sB, W2, a);
    // psp+spike+POOL fused: 131072 -> pooled 32768 into sA
    psp_spike_kernel<16><<<1024,128>>>(a, sA, 131072);
    // s4 spikes
    psp_spike_kernel<0><<<256,128>>>(sA, sB, 32768);

    // L5: conv 3x3 pad1 [16,32,8,8] -> [16,64,8,8]  (t x4, CO_T=8: 8 groups)
    conv3_kernel<32,8,64,8,8,8,8><<<dim3(4,8,128),160>>>(sB, W3, a);
    // s5 spikes
    psp_spike_kernel<0><<<512,128>>>(a, sA, 65536);

    // dense readout (split-K x4) + combine + final psp/spike into d_out
    dense_partial_kernel<<<dim3(16,10,4),320>>>(sA, Wf, up);
    dense_combine_kernel<<<188,256>>>(up, u);
    psp_spike_kernel<0><<<2,128>>>(u, (float*)d_out, 160);
}